// round 5
// baseline (speedup 1.0000x reference)
#include <cuda_runtime.h>
#include <cuda_bf16.h>
#include <cstdint>

// ---------------------------------------------------------------------------
// OnlyLinear chain collapsed to y = x @ Mf + cf.
//  Kernel 1 (collapse_all): every block redundantly folds the small chain
//    R = A3..A8 (10x10) -> Q = A2@R (31x10) -> S = A1@Q (69x10), then computes
//    its coalesced slice of Mf = A0@S. Block 0 folds the biases -> cf.
//  Kernel 2 (mlp_main): warp = 4 rows x 8-lane k-split. Direct LDG.128 on x
//    (coalesced, no staging, no loop syncs), M broadcast from smem SoA,
//    fma.rn.f32x2 accumulation, 3-step packed butterfly reduce over 8 lanes.
// ---------------------------------------------------------------------------

#define BSZ     65536
#define KDIM    784
#define NOUT    10
#define TPB     256

typedef unsigned long long u64;

// __device__ scratch (allocation-free rule)
__device__ float g_Mf[KDIM * NOUT];       // collapsed matrix, row-major [k][j]
__device__ float g_cf[NOUT];              // collapsed bias

// ---- packed f32x2 helpers --------------------------------------------------
__device__ __forceinline__ u64 ffma2(u64 a, u64 b, u64 c) {
    u64 d;
    asm("fma.rn.f32x2 %0, %1, %2, %3;" : "=l"(d) : "l"(a), "l"(b), "l"(c));
    return d;
}
__device__ __forceinline__ u64 fadd2(u64 a, u64 b) {
    u64 d;
    asm("add.rn.f32x2 %0, %1, %2;" : "=l"(d) : "l"(a), "l"(b));
    return d;
}
__device__ __forceinline__ float2 unpack2(u64 v) {
    float2 r;
    asm("mov.b64 {%0, %1}, %2;" : "=f"(r.x), "=f"(r.y) : "l"(v));
    return r;
}
__device__ __forceinline__ u64 shfl_xor_u64(u64 v, int m) {
    unsigned lo = (unsigned)v, hi = (unsigned)(v >> 32);
    lo = __shfl_xor_sync(0xffffffffu, lo, m);
    hi = __shfl_xor_sync(0xffffffffu, hi, m);
    return ((u64)hi << 32) | lo;
}

// ---------------------------------------------------------------------------
// collapse_all: 31 blocks x 256 thr. Redundant small fold per block, then the
// block's slice of Mf (coalesced W0 reads). Block 0 also folds biases.
// ---------------------------------------------------------------------------
__global__ void collapse_all(const float* __restrict__ W0, const float* __restrict__ b0,
                             const float* __restrict__ W1, const float* __restrict__ b1,
                             const float* __restrict__ W2, const float* __restrict__ b2,
                             const float* __restrict__ W3, const float* __restrict__ b3,
                             const float* __restrict__ W4, const float* __restrict__ b4,
                             const float* __restrict__ W5, const float* __restrict__ b5,
                             const float* __restrict__ W6, const float* __restrict__ b6,
                             const float* __restrict__ W7, const float* __restrict__ b7,
                             const float* __restrict__ W8, const float* __restrict__ b8) {
    __shared__ float R[2][100];      // R[k*10+j]
    __shared__ float Q[31 * 10];
    __shared__ float S[69 * 10];
    __shared__ float c1s[31];
    __shared__ float cs[2][10];
    const int t = threadIdx.x;

    // R init = A3: R[k][j] = W3[j][k]
    if (t < 100) R[0][t] = W3[(t % 10) * 10 + (t / 10)];
    __syncthreads();

    // fold A4..A8 into R
    const float* Wf[5] = {W4, W5, W6, W7, W8};
    int cur = 0;
    #pragma unroll 1
    for (int l = 0; l < 5; ++l) {
        const float* W = Wf[l];
        int nxt = cur ^ 1;
        if (t < 100) {
            int k = t / 10, j = t % 10;
            float s = 0.f;
            #pragma unroll
            for (int m = 0; m < 10; ++m)
                s = fmaf(R[cur][k * 10 + m], W[j * 10 + m], s);
            R[nxt][t] = s;
        }
        __syncthreads();
        cur = nxt;
    }

    // Q[k][j] = sum_m W2[m*31+k] * R[m][j]
    for (int e = t; e < 310; e += TPB) {
        int k = e / 10, j = e % 10;
        float s = 0.f;
        #pragma unroll
        for (int m = 0; m < 10; ++m)
            s = fmaf(W2[m * 31 + k], R[cur][m * 10 + j], s);
        Q[e] = s;
    }
    __syncthreads();

    // S[k][j] = sum_m W1[m*69+k] * Q[m][j]
    for (int e = t; e < 690; e += TPB) {
        int k = e / 10, j = e % 10;
        float s = 0.f;
        #pragma unroll 8
        for (int m = 0; m < 31; ++m)
            s = fmaf(W1[m * 69 + k], Q[m * 10 + j], s);
        S[e] = s;
    }
    __syncthreads();

    // this block's Mf slice: e -> (j = e/784, i = e%784); consecutive t ->
    // consecutive i -> coalesced W0[k*784+i]
    {
        int e = blockIdx.x * TPB + t;
        if (e < KDIM * NOUT) {
            int j = e / KDIM, i = e % KDIM;
            float s = 0.f;
            #pragma unroll 8
            for (int k = 0; k < 69; ++k)
                s = fmaf(W0[k * KDIM + i], S[k * 10 + j], s);
            g_Mf[i * 10 + j] = s;
        }
    }

    // bias fold (block 0 only; uniform branch, syncs are block-local)
    if (blockIdx.x == 0) {
        if (t < 31) {
            float s = b1[t];
            for (int k = 0; k < 69; ++k) s = fmaf(b0[k], W1[t * 69 + k], s);
            c1s[t] = s;
        }
        __syncthreads();
        if (t < 10) {
            float s = b2[t];
            for (int m = 0; m < 31; ++m) s = fmaf(c1s[m], W2[t * 31 + m], s);
            cs[0][t] = s;
        }
        __syncthreads();
        const float* Wl[6] = {W3, W4, W5, W6, W7, W8};
        const float* bl[6] = {b3, b4, b5, b6, b7, b8};
        int cb = 0;
        #pragma unroll 1
        for (int l = 0; l < 6; ++l) {
            int nb = cb ^ 1;
            if (t < 10) {
                float s = bl[l][t];
                #pragma unroll
                for (int m = 0; m < 10; ++m)
                    s = fmaf(cs[cb][m], Wl[l][t * 10 + m], s);
                cs[nb][t] = s;
            }
            __syncthreads();
            cb = nb;
        }
        if (t < 10) g_cf[t] = cs[cb][t];
    }
}

// ---------------------------------------------------------------------------
// mlp_main: out[65536,10] = x @ Mf + cf
//  warp: 4 rows (r = lane>>3) x 8 k-lanes (s = lane&7)
//  per iter (32 k per warp): lane loads its row's 16B of x (LDG.128,
//  coalesced per r-group), 10 x 16B of M (smem broadcast), 20 FFMA2.
// ---------------------------------------------------------------------------
__global__ __launch_bounds__(TPB, 3)
void mlp_main(const float* __restrict__ x, float* __restrict__ out) {
    __shared__ float Msm[NOUT * KDIM];     // SoA: Msm[j*784 + k]
    __shared__ float cfs[NOUT];

    const int t = threadIdx.x;
    for (int i = t; i < KDIM * NOUT; i += TPB) {   // coalesced g_Mf read
        int k = i / 10, j = i % 10;
        Msm[j * KDIM + k] = g_Mf[i];
    }
    if (t < NOUT) cfs[t] = g_cf[t];
    __syncthreads();

    const int lane = t & 31;
    const int warp = t >> 5;
    const int r = lane >> 3;
    const int s = lane & 7;
    const int row = (blockIdx.x * 8 + warp) * 4 + r;   // 32 rows / block
    const float* xr = x + (size_t)row * KDIM + (s << 2);
    const float* mp = Msm + (s << 2);

    u64 acc[NOUT];
    #pragma unroll
    for (int j = 0; j < NOUT; ++j) acc[j] = 0ULL;

    // 24 full iterations of 32 k
    #pragma unroll 4
    for (int kb = 0; kb < 768; kb += 32) {
        ulonglong2 xq = *(const ulonglong2*)(xr + kb);   // (k,k+1),(k+2,k+3)
        #pragma unroll
        for (int j = 0; j < NOUT; ++j) {
            ulonglong2 mq = *(const ulonglong2*)(mp + j * KDIM + kb);
            acc[j] = ffma2(xq.x, mq.x, acc[j]);
            acc[j] = ffma2(xq.y, mq.y, acc[j]);
        }
    }
    // tail: k = 768..783 handled by lanes s<4
    if (s < 4) {
        ulonglong2 xq = *(const ulonglong2*)(xr + 768);
        #pragma unroll
        for (int j = 0; j < NOUT; ++j) {
            ulonglong2 mq = *(const ulonglong2*)(mp + j * KDIM + 768);
            acc[j] = ffma2(xq.x, mq.x, acc[j]);
            acc[j] = ffma2(xq.y, mq.y, acc[j]);
        }
    }

    // butterfly over the 8 k-lanes of this row (packed adds)
    #pragma unroll
    for (int off = 1; off <= 4; off <<= 1)
        #pragma unroll
        for (int j = 0; j < NOUT; ++j)
            acc[j] = fadd2(acc[j], shfl_xor_u64(acc[j], off));

    if (s == 0) {
        float res[NOUT];
        #pragma unroll
        for (int j = 0; j < NOUT; ++j) {
            float2 p = unpack2(acc[j]);
            res[j] = p.x + p.y + cfs[j];
        }
        float* op = out + (size_t)row * NOUT;
        #pragma unroll
        for (int p2 = 0; p2 < 5; ++p2)
            *(float2*)(op + 2 * p2) = make_float2(res[2 * p2], res[2 * p2 + 1]);
    }
}

// ---------------------------------------------------------------------------
extern "C" void kernel_launch(void* const* d_in, const int* in_sizes, int n_in,
                              void* d_out, int out_size) {
    const float* x  = (const float*)d_in[0];
    const float* W0 = (const float*)d_in[1];
    const float* b0 = (const float*)d_in[2];
    const float* W1 = (const float*)d_in[3];
    const float* b1 = (const float*)d_in[4];
    const float* W2 = (const float*)d_in[5];
    const float* b2 = (const float*)d_in[6];
    const float* W3 = (const float*)d_in[7];
    const float* b3 = (const float*)d_in[8];
    const float* W4 = (const float*)d_in[9];
    const float* b4 = (const float*)d_in[10];
    const float* W5 = (const float*)d_in[11];
    const float* b5 = (const float*)d_in[12];
    const float* W6 = (const float*)d_in[13];
    const float* b6 = (const float*)d_in[14];
    const float* W7 = (const float*)d_in[15];
    const float* b7 = (const float*)d_in[16];
    const float* W8 = (const float*)d_in[17];
    const float* b8 = (const float*)d_in[18];
    float* out = (float*)d_out;

    collapse_all<<<(KDIM * NOUT + TPB - 1) / TPB, TPB>>>(
        W0, b0, W1, b1, W2, b2, W3, b3, W4, b4,
        W5, b5, W6, b6, W7, b7, W8, b8);

    mlp_main<<<BSZ / 32, TPB>>>(x, out);   // 2048 blocks, 32 rows/block
}

// round 7
// speedup vs baseline: 1.3689x; 1.3689x over previous
#include <cuda_runtime.h>
#include <cuda_bf16.h>
#include <cstdint>

// ---------------------------------------------------------------------------
// y = x @ Mf + cf  (exact collapse of the 9-layer linear chain)
//  Kernel 1 (collapse_all, 31 blocks): smem-preloaded right-assoc fold
//    R = A3..A8 -> Q = A2@R -> S = A1@Q, then per-block slice of Mf = A0@S.
//  Kernel 2 (mlp_main): warp = 4 r-groups x 8 k-lanes, 4 rows per lane
//    (16 rows/warp) to amortize M LDS.128 wavefronts; direct coalesced
//    LDG.128 on x, fma.rn.f32x2 accumulation, packed butterfly over 8 lanes.
// ---------------------------------------------------------------------------

#define BSZ     65536
#define KDIM    784
#define NOUT    10
#define TPB     256
#define RPL     4              // rows per lane
#define ROWS_PER_BLOCK (8 * 4 * RPL)   // 8 warps * 4 r-groups * RPL = 128

typedef unsigned long long u64;

__device__ float g_Mf[KDIM * NOUT];   // collapsed matrix, row-major [k][j]
__device__ float g_cf[NOUT];          // collapsed bias

// ---- packed f32x2 helpers --------------------------------------------------
__device__ __forceinline__ u64 ffma2(u64 a, u64 b, u64 c) {
    u64 d;
    asm("fma.rn.f32x2 %0, %1, %2, %3;" : "=l"(d) : "l"(a), "l"(b), "l"(c));
    return d;
}
__device__ __forceinline__ u64 fadd2(u64 a, u64 b) {
    u64 d;
    asm("add.rn.f32x2 %0, %1, %2;" : "=l"(d) : "l"(a), "l"(b));
    return d;
}
__device__ __forceinline__ float2 unpack2(u64 v) {
    float2 r;
    asm("mov.b64 {%0, %1}, %2;" : "=f"(r.x), "=f"(r.y) : "l"(v));
    return r;
}
__device__ __forceinline__ u64 shfl_xor_u64(u64 v, int m) {
    unsigned lo = (unsigned)v, hi = (unsigned)(v >> 32);
    lo = __shfl_xor_sync(0xffffffffu, lo, m);
    hi = __shfl_xor_sync(0xffffffffu, hi, m);
    return ((u64)hi << 32) | lo;
}

// ---------------------------------------------------------------------------
// collapse_all: 31 blocks x 256. All small weights preloaded to smem in one
// parallel burst; fold chain runs out of smem; block computes its Mf slice.
// ---------------------------------------------------------------------------
#define SW1   0        // 2139  (W1: 31x69)
#define SW2   2144     // 310   (W2: 10x31)
#define SW3   2464     // 6*100 (W3..W8)
#define SB0   3072     // 69
#define SB1   3152     // 31
#define SBS   3184     // 7*10  (b2..b8)
#define SWTOT 3264

__global__ void collapse_all(const float* __restrict__ W0, const float* __restrict__ b0,
                             const float* __restrict__ W1, const float* __restrict__ b1,
                             const float* __restrict__ W2, const float* __restrict__ b2,
                             const float* __restrict__ W3, const float* __restrict__ b3,
                             const float* __restrict__ W4, const float* __restrict__ b4,
                             const float* __restrict__ W5, const float* __restrict__ b5,
                             const float* __restrict__ W6, const float* __restrict__ b6,
                             const float* __restrict__ W7, const float* __restrict__ b7,
                             const float* __restrict__ W8, const float* __restrict__ b8) {
    __shared__ float sw[SWTOT];
    __shared__ float R[2][100];
    __shared__ float Q[31 * 10];
    __shared__ float S[69 * 10];
    __shared__ float c1s[31];
    __shared__ float cs[2][10];
    const int t = threadIdx.x;

    // ---- parallel preload of all small operands (independent LDGs) ----
    for (int i = t; i < 2139; i += TPB) sw[SW1 + i] = W1[i];
    for (int i = t; i < 310;  i += TPB) sw[SW2 + i] = W2[i];     // FIXED: full 310
    {   // W3..W8 : 600 floats
        const float* Wsrc[6] = {W3, W4, W5, W6, W7, W8};
        for (int i = t; i < 600; i += TPB) sw[SW3 + i] = Wsrc[i / 100][i % 100];
    }
    if (t < 69)  sw[SB0 + t] = b0[t];
    if (t < 31)  sw[SB1 + t] = b1[t];
    {   const float* bsrc[7] = {b2, b3, b4, b5, b6, b7, b8};
        if (t < 70) sw[SBS + t] = bsrc[t / 10][t % 10];
    }
    __syncthreads();

    // ---- R = A3, fold A4..A8 (all from smem) ----
    if (t < 100) R[0][t] = sw[SW3 + (t % 10) * 10 + (t / 10)];  // A3[k][j]=W3[j][k]
    __syncthreads();
    int cur = 0;
    #pragma unroll 1
    for (int l = 1; l < 6; ++l) {           // W4..W8 at SW3 + l*100
        int nxt = cur ^ 1;
        if (t < 100) {
            int k = t / 10, j = t % 10;
            float s = 0.f;
            #pragma unroll
            for (int m = 0; m < 10; ++m)
                s = fmaf(R[cur][k * 10 + m], sw[SW3 + l * 100 + j * 10 + m], s);
            R[nxt][t] = s;
        }
        __syncthreads();
        cur = nxt;
    }

    // ---- Q[k][j] = sum_m W2[m][k] * R[m][j]  (31x10) ----
    for (int e = t; e < 310; e += TPB) {                        // FIXED: full 310
        int k = e / 10, j = e % 10;
        float s = 0.f;
        #pragma unroll
        for (int m = 0; m < 10; ++m)
            s = fmaf(sw[SW2 + m * 31 + k], R[cur][m * 10 + j], s);
        Q[e] = s;
    }
    __syncthreads();

    // ---- S[k][j] = sum_m W1[m][k] * Q[m][j]  (69x10) ----
    for (int e = t; e < 690; e += TPB) {
        int k = e / 10, j = e % 10;
        float s0 = 0.f, s1 = 0.f, s2 = 0.f, s3 = 0.f;
        #pragma unroll
        for (int m = 0; m < 28; m += 4) {
            s0 = fmaf(sw[SW1 + (m + 0) * 69 + k], Q[(m + 0) * 10 + j], s0);
            s1 = fmaf(sw[SW1 + (m + 1) * 69 + k], Q[(m + 1) * 10 + j], s1);
            s2 = fmaf(sw[SW1 + (m + 2) * 69 + k], Q[(m + 2) * 10 + j], s2);
            s3 = fmaf(sw[SW1 + (m + 3) * 69 + k], Q[(m + 3) * 10 + j], s3);
        }
        #pragma unroll
        for (int m = 28; m < 31; ++m)
            s0 = fmaf(sw[SW1 + m * 69 + k], Q[m * 10 + j], s0);
        S[e] = (s0 + s1) + (s2 + s3);
    }
    __syncthreads();

    // ---- this block's Mf slice: Mf[i][j] = sum_k W0[k][i] * S[k][j] ----
    {
        int e = blockIdx.x * TPB + t;
        if (e < KDIM * NOUT) {
            int j = e / KDIM, i = e % KDIM;       // consecutive t -> coalesced W0
            float s0 = 0.f, s1 = 0.f, s2 = 0.f, s3 = 0.f;
            #pragma unroll
            for (int k = 0; k < 68; k += 4) {
                s0 = fmaf(W0[(k + 0) * KDIM + i], S[(k + 0) * 10 + j], s0);
                s1 = fmaf(W0[(k + 1) * KDIM + i], S[(k + 1) * 10 + j], s1);
                s2 = fmaf(W0[(k + 2) * KDIM + i], S[(k + 2) * 10 + j], s2);
                s3 = fmaf(W0[(k + 3) * KDIM + i], S[(k + 3) * 10 + j], s3);
            }
            s0 = fmaf(W0[68 * KDIM + i], S[68 * 10 + j], s0);
            g_Mf[i * 10 + j] = (s0 + s1) + (s2 + s3);
        }
    }

    // ---- bias fold (block 0; block-uniform branch, block-local syncs) ----
    if (blockIdx.x == 0) {
        if (t < 31) {
            float s = sw[SB1 + t];
            for (int k = 0; k < 69; ++k)
                s = fmaf(sw[SB0 + k], sw[SW1 + t * 69 + k], s);
            c1s[t] = s;
        }
        __syncthreads();
        if (t < 10) {
            float s = sw[SBS + t];                   // b2
            for (int m = 0; m < 31; ++m)
                s = fmaf(c1s[m], sw[SW2 + t * 31 + m], s);
            cs[0][t] = s;
        }
        __syncthreads();
        int cb = 0;
        #pragma unroll 1
        for (int l = 0; l < 6; ++l) {                // A3..A8, b3..b8
            int nb = cb ^ 1;
            if (t < 10) {
                float s = sw[SBS + (l + 1) * 10 + t];
                #pragma unroll
                for (int m = 0; m < 10; ++m)
                    s = fmaf(cs[cb][m], sw[SW3 + l * 100 + t * 10 + m], s);
                cs[nb][t] = s;
            }
            __syncthreads();
            cb = nb;
        }
        if (t < 10) g_cf[t] = cs[cb][t];
    }
}

// ---------------------------------------------------------------------------
// mlp_main: out[65536,10] = x @ Mf + cf
//  lane = (r = lane>>3, s = lane&7); lane handles RPL=4 consecutive rows.
//  Per iter (32 k): 4 LDG.128 on x (coalesced per r-group), 10 LDS.128 on M
//  (amortized over 16 rows/warp), 80 FFMA2.
// ---------------------------------------------------------------------------
__global__ __launch_bounds__(TPB, 2)
void mlp_main(const float* __restrict__ x, float* __restrict__ out) {
    __shared__ float Msm[NOUT * KDIM];     // SoA: Msm[j*784 + k]
    __shared__ float cfs[NOUT];

    const int t = threadIdx.x;
    for (int i = t; i < KDIM * NOUT; i += TPB) {   // coalesced g_Mf read
        int k = i / 10, j = i % 10;
        Msm[j * KDIM + k] = g_Mf[i];
    }
    if (t < NOUT) cfs[t] = g_cf[t];
    __syncthreads();

    const int lane = t & 31;
    const int warp = t >> 5;
    const int r = lane >> 3;
    const int s = lane & 7;
    const int row0 = blockIdx.x * ROWS_PER_BLOCK + warp * (4 * RPL) + r * RPL;
    const float* xr = x + (size_t)row0 * KDIM + (s << 2);
    const float* mp = Msm + (s << 2);

    u64 acc[RPL][NOUT];
    #pragma unroll
    for (int q = 0; q < RPL; ++q)
        #pragma unroll
        for (int j = 0; j < NOUT; ++j) acc[q][j] = 0ULL;

    // 24 full iterations of 32 k
    #pragma unroll 2
    for (int kb = 0; kb < 768; kb += 32) {
        ulonglong2 xq[RPL];
        #pragma unroll
        for (int q = 0; q < RPL; ++q)
            xq[q] = *(const ulonglong2*)(xr + q * KDIM + kb);
        #pragma unroll
        for (int j = 0; j < NOUT; ++j) {
            ulonglong2 mq = *(const ulonglong2*)(mp + j * KDIM + kb);
            #pragma unroll
            for (int q = 0; q < RPL; ++q) {
                acc[q][j] = ffma2(xq[q].x, mq.x, acc[q][j]);
                acc[q][j] = ffma2(xq[q].y, mq.y, acc[q][j]);
            }
        }
    }
    // tail: k = 768..783 covered by lanes s<4
    if (s < 4) {
        ulonglong2 xq[RPL];
        #pragma unroll
        for (int q = 0; q < RPL; ++q)
            xq[q] = *(const ulonglong2*)(xr + q * KDIM + 768);
        #pragma unroll
        for (int j = 0; j < NOUT; ++j) {
            ulonglong2 mq = *(const ulonglong2*)(mp + j * KDIM + 768);
            #pragma unroll
            for (int q = 0; q < RPL; ++q) {
                acc[q][j] = ffma2(xq[q].x, mq.x, acc[q][j]);
                acc[q][j] = ffma2(xq[q].y, mq.y, acc[q][j]);
            }
        }
    }

    // butterfly over the 8 k-lanes (packed adds; xor 1,2,4 stays in-group)
    #pragma unroll
    for (int off = 1; off <= 4; off <<= 1)
        #pragma unroll
        for (int q = 0; q < RPL; ++q)
            #pragma unroll
            for (int j = 0; j < NOUT; ++j)
                acc[q][j] = fadd2(acc[q][j], shfl_xor_u64(acc[q][j], off));

    if (s == 0) {
        #pragma unroll
        for (int q = 0; q < RPL; ++q) {
            float res[NOUT];
            #pragma unroll
            for (int j = 0; j < NOUT; ++j) {
                float2 p = unpack2(acc[q][j]);
                res[j] = p.x + p.y + cfs[j];
            }
            float* op = out + (size_t)(row0 + q) * NOUT;
            #pragma unroll
            for (int p2 = 0; p2 < 5; ++p2)
                *(float2*)(op + 2 * p2) = make_float2(res[2 * p2], res[2 * p2 + 1]);
        }
    }
}

// ---------------------------------------------------------------------------
extern "C" void kernel_launch(void* const* d_in, const int* in_sizes, int n_in,
                              void* d_out, int out_size) {
    const float* x  = (const float*)d_in[0];
    const float* W0 = (const float*)d_in[1];
    const float* b0 = (const float*)d_in[2];
    const float* W1 = (const float*)d_in[3];
    const float* b1 = (const float*)d_in[4];
    const float* W2 = (const float*)d_in[5];
    const float* b2 = (const float*)d_in[6];
    const float* W3 = (const float*)d_in[7];
    const float* b3 = (const float*)d_in[8];
    const float* W4 = (const float*)d_in[9];
    const float* b4 = (const float*)d_in[10];
    const float* W5 = (const float*)d_in[11];
    const float* b5 = (const float*)d_in[12];
    const float* W6 = (const float*)d_in[13];
    const float* b6 = (const float*)d_in[14];
    const float* W7 = (const float*)d_in[15];
    const float* b7 = (const float*)d_in[16];
    const float* W8 = (const float*)d_in[17];
    const float* b8 = (const float*)d_in[18];
    float* out = (float*)d_out;

    collapse_all<<<(KDIM * NOUT + TPB - 1) / TPB, TPB>>>(
        W0, b0, W1, b1, W2, b2, W3, b3, W4, b4,
        W5, b5, W6, b6, W7, b7, W8, b8);

    mlp_main<<<BSZ / ROWS_PER_BLOCK, TPB>>>(x, out);   // 512 blocks
}

// round 8
// speedup vs baseline: 1.5940x; 1.1644x over previous
#include <cuda_runtime.h>
#include <cuda_bf16.h>
#include <cstdint>

// ---------------------------------------------------------------------------
// y = x @ Mf + cf  (exact collapse of the 9-layer linear chain)
//  collapse_all (31 blocks): smem-preloaded right-assoc fold -> g_Mf, g_cf.
//  mlp_main: warp = 4 r-groups x 8 k-lanes, RPL=4 rows/lane (16 rows/warp).
//   fma.rn.f32x2 packs the J dimension: acc[q][jp] = (y[2jp], y[2jp+1]);
//   halves accumulator registers (80 -> 40) vs k-packing -> 20 warps/SM.
//   M in smem, k-quad tiled, pitch 44 floats -> conflict-free LDS.128.
// ---------------------------------------------------------------------------

#define BSZ     65536
#define KDIM    784
#define NOUT    10
#define CTPB    256           // collapse threads
#define MTPB    128           // main threads (4 warps)
#define RPL     4             // rows per lane
#define ROWS_PER_BLOCK (4 * 4 * RPL)   // 4 warps * 4 r-groups * RPL = 64
#define QPITCH  44            // floats per k-quad in smem M layout
#define NQUAD   196           // 784/4

typedef unsigned long long u64;

__device__ float g_Mf[KDIM * NOUT];   // collapsed matrix, row-major [k][j]
__device__ float g_cf[NOUT];          // collapsed bias

// ---- packed f32x2 helpers --------------------------------------------------
__device__ __forceinline__ u64 ffma2(u64 a, u64 b, u64 c) {
    u64 d;
    asm("fma.rn.f32x2 %0, %1, %2, %3;" : "=l"(d) : "l"(a), "l"(b), "l"(c));
    return d;
}
__device__ __forceinline__ u64 fadd2(u64 a, u64 b) {
    u64 d;
    asm("add.rn.f32x2 %0, %1, %2;" : "=l"(d) : "l"(a), "l"(b));
    return d;
}
__device__ __forceinline__ u64 pack2(float a, float b) {
    u64 d;
    asm("mov.b64 %0, {%1, %2};" : "=l"(d) : "f"(a), "f"(b));
    return d;
}
__device__ __forceinline__ u64 shfl_xor_u64(u64 v, int m) {
    unsigned lo = (unsigned)v, hi = (unsigned)(v >> 32);
    lo = __shfl_xor_sync(0xffffffffu, lo, m);
    hi = __shfl_xor_sync(0xffffffffu, hi, m);
    return ((u64)hi << 32) | lo;
}

// ---------------------------------------------------------------------------
// collapse_all: unchanged from R7 (passing, ~5us)
// ---------------------------------------------------------------------------
#define SW1   0
#define SW2   2144
#define SW3   2464
#define SB0   3072
#define SB1   3152
#define SBS   3184
#define SWTOT 3264

__global__ void collapse_all(const float* __restrict__ W0, const float* __restrict__ b0,
                             const float* __restrict__ W1, const float* __restrict__ b1,
                             const float* __restrict__ W2, const float* __restrict__ b2,
                             const float* __restrict__ W3, const float* __restrict__ b3,
                             const float* __restrict__ W4, const float* __restrict__ b4,
                             const float* __restrict__ W5, const float* __restrict__ b5,
                             const float* __restrict__ W6, const float* __restrict__ b6,
                             const float* __restrict__ W7, const float* __restrict__ b7,
                             const float* __restrict__ W8, const float* __restrict__ b8) {
    __shared__ float sw[SWTOT];
    __shared__ float R[2][100];
    __shared__ float Q[31 * 10];
    __shared__ float S[69 * 10];
    __shared__ float c1s[31];
    __shared__ float cs[2][10];
    const int t = threadIdx.x;

    for (int i = t; i < 2139; i += CTPB) sw[SW1 + i] = W1[i];
    for (int i = t; i < 310;  i += CTPB) sw[SW2 + i] = W2[i];
    {   const float* Wsrc[6] = {W3, W4, W5, W6, W7, W8};
        for (int i = t; i < 600; i += CTPB) sw[SW3 + i] = Wsrc[i / 100][i % 100];
    }
    if (t < 69)  sw[SB0 + t] = b0[t];
    if (t < 31)  sw[SB1 + t] = b1[t];
    {   const float* bsrc[7] = {b2, b3, b4, b5, b6, b7, b8};
        if (t < 70) sw[SBS + t] = bsrc[t / 10][t % 10];
    }
    __syncthreads();

    if (t < 100) R[0][t] = sw[SW3 + (t % 10) * 10 + (t / 10)];
    __syncthreads();
    int cur = 0;
    #pragma unroll 1
    for (int l = 1; l < 6; ++l) {
        int nxt = cur ^ 1;
        if (t < 100) {
            int k = t / 10, j = t % 10;
            float s = 0.f;
            #pragma unroll
            for (int m = 0; m < 10; ++m)
                s = fmaf(R[cur][k * 10 + m], sw[SW3 + l * 100 + j * 10 + m], s);
            R[nxt][t] = s;
        }
        __syncthreads();
        cur = nxt;
    }

    for (int e = t; e < 310; e += CTPB) {
        int k = e / 10, j = e % 10;
        float s = 0.f;
        #pragma unroll
        for (int m = 0; m < 10; ++m)
            s = fmaf(sw[SW2 + m * 31 + k], R[cur][m * 10 + j], s);
        Q[e] = s;
    }
    __syncthreads();

    for (int e = t; e < 690; e += CTPB) {
        int k = e / 10, j = e % 10;
        float s0 = 0.f, s1 = 0.f, s2 = 0.f, s3 = 0.f;
        #pragma unroll
        for (int m = 0; m < 28; m += 4) {
            s0 = fmaf(sw[SW1 + (m + 0) * 69 + k], Q[(m + 0) * 10 + j], s0);
            s1 = fmaf(sw[SW1 + (m + 1) * 69 + k], Q[(m + 1) * 10 + j], s1);
            s2 = fmaf(sw[SW1 + (m + 2) * 69 + k], Q[(m + 2) * 10 + j], s2);
            s3 = fmaf(sw[SW1 + (m + 3) * 69 + k], Q[(m + 3) * 10 + j], s3);
        }
        #pragma unroll
        for (int m = 28; m < 31; ++m)
            s0 = fmaf(sw[SW1 + m * 69 + k], Q[m * 10 + j], s0);
        S[e] = (s0 + s1) + (s2 + s3);
    }
    __syncthreads();

    {
        int e = blockIdx.x * CTPB + t;
        if (e < KDIM * NOUT) {
            int j = e / KDIM, i = e % KDIM;
            float s0 = 0.f, s1 = 0.f, s2 = 0.f, s3 = 0.f;
            #pragma unroll
            for (int k = 0; k < 68; k += 4) {
                s0 = fmaf(W0[(k + 0) * KDIM + i], S[(k + 0) * 10 + j], s0);
                s1 = fmaf(W0[(k + 1) * KDIM + i], S[(k + 1) * 10 + j], s1);
                s2 = fmaf(W0[(k + 2) * KDIM + i], S[(k + 2) * 10 + j], s2);
                s3 = fmaf(W0[(k + 3) * KDIM + i], S[(k + 3) * 10 + j], s3);
            }
            s0 = fmaf(W0[68 * KDIM + i], S[68 * 10 + j], s0);
            g_Mf[i * 10 + j] = (s0 + s1) + (s2 + s3);
        }
    }

    if (blockIdx.x == 0) {
        if (t < 31) {
            float s = sw[SB1 + t];
            for (int k = 0; k < 69; ++k)
                s = fmaf(sw[SB0 + k], sw[SW1 + t * 69 + k], s);
            c1s[t] = s;
        }
        __syncthreads();
        if (t < 10) {
            float s = sw[SBS + t];
            for (int m = 0; m < 31; ++m)
                s = fmaf(c1s[m], sw[SW2 + t * 31 + m], s);
            cs[0][t] = s;
        }
        __syncthreads();
        int cb = 0;
        #pragma unroll 1
        for (int l = 0; l < 6; ++l) {
            int nb = cb ^ 1;
            if (t < 10) {
                float s = sw[SBS + (l + 1) * 10 + t];
                #pragma unroll
                for (int m = 0; m < 10; ++m)
                    s = fmaf(cs[cb][m], sw[SW3 + l * 100 + t * 10 + m], s);
                cs[nb][t] = s;
            }
            __syncthreads();
            cb = nb;
        }
        if (t < 10) g_cf[t] = cs[cb][t];
    }
}

// ---------------------------------------------------------------------------
// mlp_main: out = x @ Mf + cf, j-pair-packed FFMA2.
//  smem M layout: Mp[quad][jp][kpos] as float pairs:
//    float offset = quad*44 + jp*8 + kpos*2 + (j&1),  quad = k/4, jp = j/2.
//  Lane s owns k-quad (kb/4 + s); stride 44 ≡ 12 (mod 32 banks) ->
//  the 8 s-lanes map to the 8 disjoint 4-bank groups -> conflict-free.
// ---------------------------------------------------------------------------
__global__ __launch_bounds__(MTPB, 5)
void mlp_main(const float* __restrict__ x, float* __restrict__ out) {
    __shared__ float Mp[NQUAD * QPITCH];   // 8624 floats = 34.5 KB
    __shared__ float cfs[NOUT];

    const int t = threadIdx.x;
    for (int i = t; i < KDIM * NOUT; i += MTPB) {   // coalesced g_Mf read
        int k = i / 10, j = i % 10;
        Mp[(k >> 2) * QPITCH + (j >> 1) * 8 + (k & 3) * 2 + (j & 1)] = g_Mf[i];
    }
    if (t < NOUT) cfs[t] = g_cf[t];
    __syncthreads();

    const int lane = t & 31;
    const int warp = t >> 5;
    const int r = lane >> 3;
    const int s = lane & 7;
    const int row0 = blockIdx.x * ROWS_PER_BLOCK + warp * (4 * RPL) + r * RPL;
    const float* xs = x + (size_t)row0 * KDIM + (s << 2);  // lane k-offset 4s
    const float* msm = Mp + s * QPITCH;                    // lane quad offset

    u64 acc[RPL][5];
    #pragma unroll
    for (int q = 0; q < RPL; ++q)
        #pragma unroll
        for (int jp = 0; jp < 5; ++jp) acc[q][jp] = 0ULL;

    // 24 full iterations of 32 k (lane covers k = kb + 4s .. +3)
    #pragma unroll 2
    for (int kb = 0; kb < 768; kb += 32) {
        // load x (LDG.128, coalesced within r-group) and pack (xk,xk)
        u64 xp[RPL][4];
        #pragma unroll
        for (int q = 0; q < RPL; ++q) {
            float4 xv = *(const float4*)(xs + q * KDIM + kb);
            xp[q][0] = pack2(xv.x, xv.x);
            xp[q][1] = pack2(xv.y, xv.y);
            xp[q][2] = pack2(xv.z, xv.z);
            xp[q][3] = pack2(xv.w, xv.w);
        }
        const float* mb = msm + (kb / 4) * QPITCH;
        #pragma unroll
        for (int jp = 0; jp < 5; ++jp) {
            ulonglong2 mA = *(const ulonglong2*)(mb + jp * 8);      // kpos 0,1
            ulonglong2 mB = *(const ulonglong2*)(mb + jp * 8 + 4);  // kpos 2,3
            #pragma unroll
            for (int q = 0; q < RPL; ++q) {
                acc[q][jp] = ffma2(xp[q][0], mA.x, acc[q][jp]);
                acc[q][jp] = ffma2(xp[q][1], mA.y, acc[q][jp]);
                acc[q][jp] = ffma2(xp[q][2], mB.x, acc[q][jp]);
                acc[q][jp] = ffma2(xp[q][3], mB.y, acc[q][jp]);
            }
        }
    }
    // tail: k = 768..783 -> quads 192..195, lanes s<4
    if (s < 4) {
        u64 xp[RPL][4];
        #pragma unroll
        for (int q = 0; q < RPL; ++q) {
            float4 xv = *(const float4*)(xs + q * KDIM + 768);
            xp[q][0] = pack2(xv.x, xv.x);
            xp[q][1] = pack2(xv.y, xv.y);
            xp[q][2] = pack2(xv.z, xv.z);
            xp[q][3] = pack2(xv.w, xv.w);
        }
        const float* mb = msm + 192 * QPITCH;
        #pragma unroll
        for (int jp = 0; jp < 5; ++jp) {
            ulonglong2 mA = *(const ulonglong2*)(mb + jp * 8);
            ulonglong2 mB = *(const ulonglong2*)(mb + jp * 8 + 4);
            #pragma unroll
            for (int q = 0; q < RPL; ++q) {
                acc[q][jp] = ffma2(xp[q][0], mA.x, acc[q][jp]);
                acc[q][jp] = ffma2(xp[q][1], mA.y, acc[q][jp]);
                acc[q][jp] = ffma2(xp[q][2], mB.x, acc[q][jp]);
                acc[q][jp] = ffma2(xp[q][3], mB.y, acc[q][jp]);
            }
        }
    }

    // butterfly over the 8 k-lanes (packed adds)
    #pragma unroll
    for (int off = 1; off <= 4; off <<= 1)
        #pragma unroll
        for (int q = 0; q < RPL; ++q)
            #pragma unroll
            for (int jp = 0; jp < 5; ++jp)
                acc[q][jp] = fadd2(acc[q][jp], shfl_xor_u64(acc[q][jp], off));

    if (s == 0) {
        u64 cf2[5];
        #pragma unroll
        for (int jp = 0; jp < 5; ++jp) cf2[jp] = pack2(cfs[2 * jp], cfs[2 * jp + 1]);
        #pragma unroll
        for (int q = 0; q < RPL; ++q) {
            u64* op = (u64*)(out + (size_t)(row0 + q) * NOUT);
            #pragma unroll
            for (int jp = 0; jp < 5; ++jp)
                op[jp] = fadd2(acc[q][jp], cf2[jp]);   // (y2jp, y2jp+1) + bias
        }
    }
}

// ---------------------------------------------------------------------------
extern "C" void kernel_launch(void* const* d_in, const int* in_sizes, int n_in,
                              void* d_out, int out_size) {
    const float* x  = (const float*)d_in[0];
    const float* W0 = (const float*)d_in[1];
    const float* b0 = (const float*)d_in[2];
    const float* W1 = (const float*)d_in[3];
    const float* b1 = (const float*)d_in[4];
    const float* W2 = (const float*)d_in[5];
    const float* b2 = (const float*)d_in[6];
    const float* W3 = (const float*)d_in[7];
    const float* b3 = (const float*)d_in[8];
    const float* W4 = (const float*)d_in[9];
    const float* b4 = (const float*)d_in[10];
    const float* W5 = (const float*)d_in[11];
    const float* b5 = (const float*)d_in[12];
    const float* W6 = (const float*)d_in[13];
    const float* b6 = (const float*)d_in[14];
    const float* W7 = (const float*)d_in[15];
    const float* b7 = (const float*)d_in[16];
    const float* W8 = (const float*)d_in[17];
    const float* b8 = (const float*)d_in[18];
    float* out = (float*)d_out;

    collapse_all<<<(KDIM * NOUT + CTPB - 1) / CTPB, CTPB>>>(
        W0, b0, W1, b1, W2, b2, W3, b3, W4, b4,
        W5, b5, W6, b6, W7, b7, W8, b8);

    mlp_main<<<BSZ / ROWS_PER_BLOCK, MTPB>>>(x, out);   // 1024 blocks x 128
}

// round 9
// speedup vs baseline: 1.6379x; 1.0276x over previous
#include <cuda_runtime.h>
#include <cuda_bf16.h>
#include <cstdint>

// ---------------------------------------------------------------------------
// y = x @ Mf + cf  (exact collapse of the 9-layer linear chain)
//  collapse_all (31 blocks): smem-preloaded right-assoc fold -> g_Mf, g_cf.
//  mlp_main: warp = 4 r-groups x 8 k-lanes, RPL=4 rows/lane (16 rows/warp).
//   x is staged warp-privately via cp.async (LDGSTS, register-free prefetch),
//   double-buffered, commit/wait_group sync only (no block barriers in loop).
//   fma.rn.f32x2 packs the J dimension (acc = (y2j, y2j+1)), 40 acc regs.
// ---------------------------------------------------------------------------

#define BSZ     65536
#define KDIM    784
#define NOUT    10
#define CTPB    256
#define MTPB    256              // 8 warps
#define RPL     4                // rows per lane
#define WROWS   16               // rows per warp
#define ROWS_PER_BLOCK 128       // 8 warps * 16
#define QPITCH  44               // floats per k-quad in M smem layout
#define NQUAD   196              // 784/4
#define XP      36               // stage pitch (floats/row): 144B, 16B-aligned
#define STGF    (WROWS * XP)     // 576 floats per warp-stage
#define NFULL   24               // full 32-k chunks; chunk 24 = 16-k tail

typedef unsigned long long u64;

__device__ float g_Mf[KDIM * NOUT];
__device__ float g_cf[NOUT];

// ---- packed f32x2 / async helpers -----------------------------------------
__device__ __forceinline__ u64 ffma2(u64 a, u64 b, u64 c) {
    u64 d;
    asm("fma.rn.f32x2 %0, %1, %2, %3;" : "=l"(d) : "l"(a), "l"(b), "l"(c));
    return d;
}
__device__ __forceinline__ u64 fadd2(u64 a, u64 b) {
    u64 d;
    asm("add.rn.f32x2 %0, %1, %2;" : "=l"(d) : "l"(a), "l"(b));
    return d;
}
__device__ __forceinline__ u64 pack2(float a, float b) {
    u64 d;
    asm("mov.b64 %0, {%1, %2};" : "=l"(d) : "f"(a), "f"(b));
    return d;
}
__device__ __forceinline__ u64 shfl_xor_u64(u64 v, int m) {
    unsigned lo = (unsigned)v, hi = (unsigned)(v >> 32);
    lo = __shfl_xor_sync(0xffffffffu, lo, m);
    hi = __shfl_xor_sync(0xffffffffu, hi, m);
    return ((u64)hi << 32) | lo;
}
__device__ __forceinline__ void cp16(unsigned dst, const float* src) {
    asm volatile("cp.async.cg.shared.global [%0], [%1], 16;" :: "r"(dst), "l"(src));
}
#define CP_COMMIT() asm volatile("cp.async.commit_group;" ::: "memory")
#define CP_WAIT1()  asm volatile("cp.async.wait_group 1;" ::: "memory")

// ---------------------------------------------------------------------------
// collapse_all: unchanged (passing, ~5us)
// ---------------------------------------------------------------------------
#define SW1   0
#define SW2   2144
#define SW3   2464
#define SB0   3072
#define SB1   3152
#define SBS   3184
#define SWTOT 3264

__global__ void collapse_all(const float* __restrict__ W0, const float* __restrict__ b0,
                             const float* __restrict__ W1, const float* __restrict__ b1,
                             const float* __restrict__ W2, const float* __restrict__ b2,
                             const float* __restrict__ W3, const float* __restrict__ b3,
                             const float* __restrict__ W4, const float* __restrict__ b4,
                             const float* __restrict__ W5, const float* __restrict__ b5,
                             const float* __restrict__ W6, const float* __restrict__ b6,
                             const float* __restrict__ W7, const float* __restrict__ b7,
                             const float* __restrict__ W8, const float* __restrict__ b8) {
    __shared__ float sw[SWTOT];
    __shared__ float R[2][100];
    __shared__ float Q[31 * 10];
    __shared__ float S[69 * 10];
    __shared__ float c1s[31];
    __shared__ float cs[2][10];
    const int t = threadIdx.x;

    for (int i = t; i < 2139; i += CTPB) sw[SW1 + i] = W1[i];
    for (int i = t; i < 310;  i += CTPB) sw[SW2 + i] = W2[i];
    {   const float* Wsrc[6] = {W3, W4, W5, W6, W7, W8};
        for (int i = t; i < 600; i += CTPB) sw[SW3 + i] = Wsrc[i / 100][i % 100];
    }
    if (t < 69)  sw[SB0 + t] = b0[t];
    if (t < 31)  sw[SB1 + t] = b1[t];
    {   const float* bsrc[7] = {b2, b3, b4, b5, b6, b7, b8};
        if (t < 70) sw[SBS + t] = bsrc[t / 10][t % 10];
    }
    __syncthreads();

    if (t < 100) R[0][t] = sw[SW3 + (t % 10) * 10 + (t / 10)];
    __syncthreads();
    int cur = 0;
    #pragma unroll 1
    for (int l = 1; l < 6; ++l) {
        int nxt = cur ^ 1;
        if (t < 100) {
            int k = t / 10, j = t % 10;
            float s = 0.f;
            #pragma unroll
            for (int m = 0; m < 10; ++m)
                s = fmaf(R[cur][k * 10 + m], sw[SW3 + l * 100 + j * 10 + m], s);
            R[nxt][t] = s;
        }
        __syncthreads();
        cur = nxt;
    }

    for (int e = t; e < 310; e += CTPB) {
        int k = e / 10, j = e % 10;
        float s = 0.f;
        #pragma unroll
        for (int m = 0; m < 10; ++m)
            s = fmaf(sw[SW2 + m * 31 + k], R[cur][m * 10 + j], s);
        Q[e] = s;
    }
    __syncthreads();

    for (int e = t; e < 690; e += CTPB) {
        int k = e / 10, j = e % 10;
        float s0 = 0.f, s1 = 0.f, s2 = 0.f, s3 = 0.f;
        #pragma unroll
        for (int m = 0; m < 28; m += 4) {
            s0 = fmaf(sw[SW1 + (m + 0) * 69 + k], Q[(m + 0) * 10 + j], s0);
            s1 = fmaf(sw[SW1 + (m + 1) * 69 + k], Q[(m + 1) * 10 + j], s1);
            s2 = fmaf(sw[SW1 + (m + 2) * 69 + k], Q[(m + 2) * 10 + j], s2);
            s3 = fmaf(sw[SW1 + (m + 3) * 69 + k], Q[(m + 3) * 10 + j], s3);
        }
        #pragma unroll
        for (int m = 28; m < 31; ++m)
            s0 = fmaf(sw[SW1 + m * 69 + k], Q[m * 10 + j], s0);
        S[e] = (s0 + s1) + (s2 + s3);
    }
    __syncthreads();

    {
        int e = blockIdx.x * CTPB + t;
        if (e < KDIM * NOUT) {
            int j = e / KDIM, i = e % KDIM;
            float s0 = 0.f, s1 = 0.f, s2 = 0.f, s3 = 0.f;
            #pragma unroll
            for (int k = 0; k < 68; k += 4) {
                s0 = fmaf(W0[(k + 0) * KDIM + i], S[(k + 0) * 10 + j], s0);
                s1 = fmaf(W0[(k + 1) * KDIM + i], S[(k + 1) * 10 + j], s1);
                s2 = fmaf(W0[(k + 2) * KDIM + i], S[(k + 2) * 10 + j], s2);
                s3 = fmaf(W0[(k + 3) * KDIM + i], S[(k + 3) * 10 + j], s3);
            }
            s0 = fmaf(W0[68 * KDIM + i], S[68 * 10 + j], s0);
            g_Mf[i * 10 + j] = (s0 + s1) + (s2 + s3);
        }
    }

    if (blockIdx.x == 0) {
        if (t < 31) {
            float s = sw[SB1 + t];
            for (int k = 0; k < 69; ++k)
                s = fmaf(sw[SB0 + k], sw[SW1 + t * 69 + k], s);
            c1s[t] = s;
        }
        __syncthreads();
        if (t < 10) {
            float s = sw[SBS + t];
            for (int m = 0; m < 31; ++m)
                s = fmaf(c1s[m], sw[SW2 + t * 31 + m], s);
            cs[0][t] = s;
        }
        __syncthreads();
        int cb = 0;
        #pragma unroll 1
        for (int l = 0; l < 6; ++l) {
            int nb = cb ^ 1;
            if (t < 10) {
                float s = sw[SBS + (l + 1) * 10 + t];
                #pragma unroll
                for (int m = 0; m < 10; ++m)
                    s = fmaf(cs[cb][m], sw[SW3 + l * 100 + t * 10 + m], s);
                cs[nb][t] = s;
            }
            __syncthreads();
            cb = nb;
        }
        if (t < 10) g_cf[t] = cs[cb][t];
    }
}

// ---------------------------------------------------------------------------
// mlp_main with cp.async double-buffered warp-private x staging.
//  dyn smem layout (floats):
//   [0 .. 8624)                  Mp   (k-quad tiled M, pitch 44)
//   [8624 .. 8624+8*2*576)       stages: warp w, buf b at 8624+(w*2+b)*576
//  +static cfs[10]
// ---------------------------------------------------------------------------
__global__ __launch_bounds__(MTPB, 3)
void mlp_main(const float* __restrict__ x, float* __restrict__ out) {
    extern __shared__ float sm[];
    float* Mp = sm;                          // 8624 floats
    __shared__ float cfs[NOUT];

    const int t    = threadIdx.x;
    const int lane = t & 31;
    const int warp = t >> 5;
    const int r    = lane >> 3;
    const int s    = lane & 7;
    const int rowbase = blockIdx.x * ROWS_PER_BLOCK + warp * WROWS;

    float* stg[2];
    stg[0] = sm + 8624 + (warp * 2 + 0) * STGF;
    stg[1] = sm + 8624 + (warp * 2 + 1) * STGF;
    unsigned stg_u32[2];
    stg_u32[0] = (unsigned)__cvta_generic_to_shared(stg[0]);
    stg_u32[1] = (unsigned)__cvta_generic_to_shared(stg[1]);

    const float* xw = x + (size_t)rowbase * KDIM;

    // ---- issue chunk 0 (overlaps with the M smem fill below) ----
    {
        #pragma unroll
        for (int i = 0; i < 4; ++i) {
            int f4  = lane + 32 * i;           // 0..127
            int row = f4 >> 3, col = (f4 & 7) << 2;
            cp16(stg_u32[0] + (row * XP + col) * 4, xw + row * KDIM + col);
        }
        CP_COMMIT();
    }

    // ---- fill M (k-quad tiled) + bias ----
    for (int i = t; i < KDIM * NOUT; i += MTPB) {
        int k = i / 10, j = i % 10;
        Mp[(k >> 2) * QPITCH + (j >> 1) * 8 + (k & 3) * 2 + (j & 1)] = g_Mf[i];
    }
    if (t < NOUT) cfs[t] = g_cf[t];
    __syncthreads();

    u64 acc[RPL][5];
    #pragma unroll
    for (int q = 0; q < RPL; ++q)
        #pragma unroll
        for (int jp = 0; jp < 5; ++jp) acc[q][jp] = 0ULL;

    const float* msm = Mp + s * QPITCH;

    #pragma unroll 1
    for (int ch = 0; ch < NFULL + 1; ++ch) {
        // prefetch chunk ch+1 (or commit an empty group to keep count)
        if (ch < NFULL - 1) {                  // next is a full chunk
            unsigned d = stg_u32[(ch + 1) & 1];
            const float* g = xw + (ch + 1) * 32;
            #pragma unroll
            for (int i = 0; i < 4; ++i) {
                int f4  = lane + 32 * i;
                int row = f4 >> 3, col = (f4 & 7) << 2;
                cp16(d + (row * XP + col) * 4, g + row * KDIM + col);
            }
        } else if (ch == NFULL - 1) {          // next is the 16-k tail
            unsigned d = stg_u32[(ch + 1) & 1];
            const float* g = xw + NFULL * 32;
            #pragma unroll
            for (int i = 0; i < 2; ++i) {
                int f4  = lane + 32 * i;       // 0..63
                int row = f4 >> 2, col = (f4 & 3) << 2;
                cp16(d + (row * XP + col) * 4, g + row * KDIM + col);
            }
        }
        CP_COMMIT();
        CP_WAIT1();                            // oldest (chunk ch) complete
        __syncwarp();

        const float* sb = stg[ch & 1] + (r * RPL) * XP + (s << 2);
        const float* mb = msm + ch * 8 * QPITCH;
        const bool active = (ch < NFULL) || (s < 4);
        if (active) {
            u64 xp[RPL][4];
            #pragma unroll
            for (int q = 0; q < RPL; ++q) {
                float4 xv = *(const float4*)(sb + q * XP);
                xp[q][0] = pack2(xv.x, xv.x);
                xp[q][1] = pack2(xv.y, xv.y);
                xp[q][2] = pack2(xv.z, xv.z);
                xp[q][3] = pack2(xv.w, xv.w);
            }
            #pragma unroll
            for (int jp = 0; jp < 5; ++jp) {
                ulonglong2 mA = *(const ulonglong2*)(mb + jp * 8);
                ulonglong2 mB = *(const ulonglong2*)(mb + jp * 8 + 4);
                #pragma unroll
                for (int q = 0; q < RPL; ++q) {
                    acc[q][jp] = ffma2(xp[q][0], mA.x, acc[q][jp]);
                    acc[q][jp] = ffma2(xp[q][1], mA.y, acc[q][jp]);
                    acc[q][jp] = ffma2(xp[q][2], mB.x, acc[q][jp]);
                    acc[q][jp] = ffma2(xp[q][3], mB.y, acc[q][jp]);
                }
            }
        }
        __syncwarp();                          // buffer reuse fence
    }

    // butterfly over the 8 k-lanes (packed adds)
    #pragma unroll
    for (int off = 1; off <= 4; off <<= 1)
        #pragma unroll
        for (int q = 0; q < RPL; ++q)
            #pragma unroll
            for (int jp = 0; jp < 5; ++jp)
                acc[q][jp] = fadd2(acc[q][jp], shfl_xor_u64(acc[q][jp], off));

    if (s == 0) {
        u64 cf2[5];
        #pragma unroll
        for (int jp = 0; jp < 5; ++jp) cf2[jp] = pack2(cfs[2 * jp], cfs[2 * jp + 1]);
        const int row0 = rowbase + r * RPL;
        #pragma unroll
        for (int q = 0; q < RPL; ++q) {
            u64* op = (u64*)(out + (size_t)(row0 + q) * NOUT);
            #pragma unroll
            for (int jp = 0; jp < 5; ++jp)
                op[jp] = fadd2(acc[q][jp], cf2[jp]);
        }
    }
}

// ---------------------------------------------------------------------------
extern "C" void kernel_launch(void* const* d_in, const int* in_sizes, int n_in,
                              void* d_out, int out_size) {
    const float* x  = (const float*)d_in[0];
    const float* W0 = (const float*)d_in[1];
    const float* b0 = (const float*)d_in[2];
    const float* W1 = (const float*)d_in[3];
    const float* b1 = (const float*)d_in[4];
    const float* W2 = (const float*)d_in[5];
    const float* b2 = (const float*)d_in[6];
    const float* W3 = (const float*)d_in[7];
    const float* b3 = (const float*)d_in[8];
    const float* W4 = (const float*)d_in[9];
    const float* b4 = (const float*)d_in[10];
    const float* W5 = (const float*)d_in[11];
    const float* b5 = (const float*)d_in[12];
    const float* W6 = (const float*)d_in[13];
    const float* b6 = (const float*)d_in[14];
    const float* W7 = (const float*)d_in[15];
    const float* b7 = (const float*)d_in[16];
    const float* W8 = (const float*)d_in[17];
    const float* b8 = (const float*)d_in[18];
    float* out = (float*)d_out;

    static bool attr_set = false;
    const int smem_bytes = (8624 + 8 * 2 * STGF) * sizeof(float);  // 71360 B
    if (!attr_set) {
        cudaFuncSetAttribute(mlp_main, cudaFuncAttributeMaxDynamicSharedMemorySize,
                             smem_bytes);
        attr_set = true;
    }

    collapse_all<<<(KDIM * NOUT + CTPB - 1) / CTPB, CTPB>>>(
        W0, b0, W1, b1, W2, b2, W3, b3, W4, b4,
        W5, b5, W6, b6, W7, b7, W8, b8);

    mlp_main<<<BSZ / ROWS_PER_BLOCK, MTPB, smem_bytes>>>(x, out);  // 512 blocks
}